// round 9
// baseline (speedup 1.0000x reference)
#include <cuda_runtime.h>
#include <math.h>

#define NB 16
#define PP 1024
#define CAP 160
#define TSEL 0.07f
#define ES (NB * PP)   /* e-plane stride in sparse tables */

static constexpr float KLOG  = 1442.6950408889634f;   // 1/(EPS*ln2)
static constexpr float NKLOG = -1442.6950408889634f;
static constexpr float LGEPS = 1e-8f;

// Persistent scratch (module globals; no runtime allocation)
__device__ float g_uK[NB * PP];
__device__ float g_vK[NB * PP];
__device__ float g_logmu2[NB * PP];
__device__ float g_lognu2[NB * PP];
__device__ float g_cmin[NB * PP];
__device__ float g_cminK[NB * PP];
__device__ float g_rminK[NB * PP];
__device__ float g_ct[CAP * NB * PP];             // (min - C)*K, e-major
__device__ unsigned short g_cidx[CAP * NB * PP];  // row index
__device__ int   g_ccnt[NB * PP];
__device__ float g_rt[CAP * NB * PP];
__device__ unsigned short g_ridx[CAP * NB * PP];  // col index
__device__ int   g_rcnt[NB * PP];
__device__ int   g_ccnt8[NB * 8 * PP];            // per-(col, rowchunk) counts
__device__ int   g_coff8[NB * 8 * PP];            // per-(col, rowchunk) offsets
__device__ float g_part[NB * 64];
__device__ float g_cost[NB];

__device__ __forceinline__ float ex2f(float x) {
    float y; asm("ex2.approx.ftz.f32 %0, %1;" : "=f"(y) : "f"(x)); return y;
}
__device__ __forceinline__ float lg2f(float x) {
    float y; asm("lg2.approx.ftz.f32 %0, %1;" : "=f"(y) : "f"(x)); return y;
}

__global__ void __launch_bounds__(256) init_k(const float* __restrict__ mu,
                                              const float* __restrict__ nu) {
    int t = blockIdx.x * blockDim.x + threadIdx.x;
    if (t < NB * PP) {
        g_logmu2[t] = log2f(mu[t] + LGEPS);
        g_lognu2[t] = log2f(nu[t] + LGEPS);
        g_uK[t] = KLOG;   // u = 1
    }
}

// Prefill sparse t-tables with -1e9 so padded entries contribute exactly 0.
__global__ void __launch_bounds__(256) pad_k() {
    int t = blockIdx.x * blockDim.x + threadIdx.x;
    if (t < CAP * NB * PP) { g_ct[t] = -1e9f; g_rt[t] = -1e9f; }
}

// ------------------------- per-column min -------------------------
__global__ void __launch_bounds__(256) colmin_k(const float* __restrict__ C) {
    const int n = blockIdx.y, cb = blockIdx.x;
    __shared__ float pm[16 * 64];
    const int tid = threadIdx.x;
    const int cg = tid & 15, rg = tid >> 4;
    const float4* Cp = (const float4*)(C + ((size_t)n << 20)
                       + (size_t)(rg * 64) * PP) + cb * 16 + cg;
    float4 mn = make_float4(1e30f, 1e30f, 1e30f, 1e30f);
#pragma unroll 8
    for (int r = 0; r < 64; ++r) {
        float4 c = Cp[r * (PP / 4)];
        mn.x = fminf(mn.x, c.x); mn.y = fminf(mn.y, c.y);
        mn.z = fminf(mn.z, c.z); mn.w = fminf(mn.w, c.w);
    }
    *(float4*)(pm + rg * 64 + cg * 4) = mn;
    __syncthreads();
    if (tid < 64) {
        float m = pm[tid];
#pragma unroll
        for (int k = 1; k < 16; ++k) m = fminf(m, pm[k * 64 + tid]);
        g_cmin[n * PP + cb * 64 + tid]  = m;
        g_cminK[n * PP + cb * 64 + tid] = KLOG * m;
    }
}

// ---------------- column compaction: count / scan / write ----------------
// Worker = (rowchunk q of 128 rows, column j). 8192 workers per batch.
__global__ void __launch_bounds__(256) colcnt_k(const float* __restrict__ C) {
    const int n = blockIdx.y;
    const int w = blockIdx.x * 256 + threadIdx.x;   // 0..8191
    const int q = w >> 10, j = w & 1023;
    const float th = g_cmin[n * PP + j] + TSEL;
    const float* Cp = C + ((size_t)n << 20) + (size_t)(q * 128) * PP + j;
    int cnt = 0;
#pragma unroll 8
    for (int r = 0; r < 128; ++r) cnt += (Cp[(size_t)r * PP] < th) ? 1 : 0;
    g_ccnt8[(n * 8 + q) * PP + j] = cnt;
}

__global__ void __launch_bounds__(256) colscan_k() {
    int t = blockIdx.x * 256 + threadIdx.x;   // 0..16383
    int n = t >> 10, j = t & 1023;
    int off = 0;
#pragma unroll
    for (int q = 0; q < 8; ++q) {
        g_coff8[(n * 8 + q) * PP + j] = off;
        off += g_ccnt8[(n * 8 + q) * PP + j];
    }
    g_ccnt[n * PP + j] = off < CAP ? off : CAP;
}

__global__ void __launch_bounds__(256) colwrite_k(const float* __restrict__ C) {
    const int n = blockIdx.y;
    const int w = blockIdx.x * 256 + threadIdx.x;
    const int q = w >> 10, j = w & 1023;
    const float mn = g_cmin[n * PP + j];
    const float th = mn + TSEL;
    const float* Cp = C + ((size_t)n << 20) + (size_t)(q * 128) * PP + j;
    int e = g_coff8[(n * 8 + q) * PP + j];
    for (int r = 0; r < 128; ++r) {
        float c = Cp[(size_t)r * PP];
        if (c < th) {
            if (e < CAP) {
                g_ct[e * ES + n * PP + j]   = (mn - c) * KLOG;
                g_cidx[e * ES + n * PP + j] = (unsigned short)(q * 128 + r);
            }
            ++e;
        }
    }
}

// ---------------- fused row min + compaction (warp per row) ----------------
__global__ void __launch_bounds__(256) rowmincompact_k(const float* __restrict__ C) {
    const int n = blockIdx.y;
    const int tid = threadIdx.x, w = tid >> 5, l = tid & 31;
    const int i = blockIdx.x * 8 + w;
    const float* Cr = C + ((size_t)n << 20) + (size_t)i * PP;
    const float4* Cr4 = (const float4*)Cr;
    float m = 1e30f;
#pragma unroll
    for (int k = 0; k < 8; ++k) {
        float4 c = Cr4[l + 32 * k];
        m = fminf(m, fminf(fminf(c.x, c.y), fminf(c.z, c.w)));
    }
#pragma unroll
    for (int o = 16; o; o >>= 1) m = fminf(m, __shfl_xor_sync(0xFFFFFFFFu, m, o));
    if (l == 0) g_rminK[n * PP + i] = KLOG * m;

    const float th = m + TSEL;
    int base = 0;
    for (int cb = 0; cb < 32; ++cb) {
        float c = Cr[cb * 32 + l];
        bool p = c < th;
        unsigned msk = __ballot_sync(0xFFFFFFFFu, p);
        int e = base + __popc(msk & ((1u << l) - 1u));
        if (p && e < CAP) {
            g_rt[e * ES + n * PP + i]   = (m - c) * KLOG;
            g_ridx[e * ES + n * PP + i] = (unsigned short)(cb * 32 + l);
        }
        base += __popc(msk);
    }
    if (l == 0) g_rcnt[n * PP + i] = base < CAP ? base : CAP;
}

// ---------------------------------------------------------------------------
// Persistent iteration kernel: 100 iterations, cluster of 8 CTAs per batch.
// Each CTA owns 128 columns (col phase) / 128 rows (row phase). u/v exchanged
// through L2 (.cv loads); barrier.cluster between half-steps (emits CCTL.IVALL).
// ---------------------------------------------------------------------------
__global__ void __launch_bounds__(128) __cluster_dims__(8, 1, 1)
iter_k() {
    const int n   = blockIdx.y;
    const int tid = threadIdx.x;
    const int gi  = n * PP + blockIdx.x * 128 + tid;
    __shared__ float sh[PP];
    __shared__ float red[4];

    const float cminK = g_cminK[gi];
    const float lognu = g_lognu2[gi];
    const float rminK = g_rminK[gi];
    const float logmu = g_logmu2[gi];
    int ccnt = g_ccnt[gi], rcnt = g_rcnt[gi];
#pragma unroll
    for (int o = 16; o; o >>= 1) {
        ccnt = max(ccnt, __shfl_xor_sync(0xFFFFFFFFu, ccnt, o));
        rcnt = max(rcnt, __shfl_xor_sync(0xFFFFFFFFu, rcnt, o));
    }
    const float* ctp = g_ct + gi;
    const unsigned short* cip = g_cidx + gi;
    const float* rtp = g_rt + gi;
    const unsigned short* rip = g_ridx + gi;

    const float4* up4 = (const float4*)(g_uK + n * PP);
    const float4* vp4 = (const float4*)(g_vK + n * PP);
    float4* shv = (float4*)sh;
    const int w = tid >> 5, l = tid & 31;

    for (int it = 0; it < 100; ++it) {
        // ---------------- col phase: u -> v ----------------
        {
            float4 a = __ldcv(up4 + tid);
            float4 b = __ldcv(up4 + 128 + tid);
            shv[tid] = a; shv[tid + 128] = b;
            float mx = fmaxf(fmaxf(fmaxf(a.x, a.y), fmaxf(a.z, a.w)),
                             fmaxf(fmaxf(b.x, b.y), fmaxf(b.z, b.w)));
#pragma unroll
            for (int o = 16; o; o >>= 1) mx = fmaxf(mx, __shfl_xor_sync(0xFFFFFFFFu, mx, o));
            if (l == 0) red[w] = mx;
            __syncthreads();
            const float Bu = fmaxf(fmaxf(red[0], red[1]), fmaxf(red[2], red[3]));
            float s = 0.f;
#pragma unroll 4
            for (int e = 0; e < ccnt; ++e) {
                float t  = ctp[e * ES];
                int  idx = cip[e * ES];
                s += ex2f(sh[idx] + (t - Bu));
            }
            g_vK[gi] = lognu - (Bu - cminK + lg2f(s));
            __threadfence();
            asm volatile("barrier.cluster.arrive.aligned;" ::: "memory");
            asm volatile("barrier.cluster.wait.aligned;"   ::: "memory");
        }
        // ---------------- row phase: v -> u ----------------
        {
            float4 a = __ldcv(vp4 + tid);
            float4 b = __ldcv(vp4 + 128 + tid);
            shv[tid] = a; shv[tid + 128] = b;
            float mx = fmaxf(fmaxf(fmaxf(a.x, a.y), fmaxf(a.z, a.w)),
                             fmaxf(fmaxf(b.x, b.y), fmaxf(b.z, b.w)));
#pragma unroll
            for (int o = 16; o; o >>= 1) mx = fmaxf(mx, __shfl_xor_sync(0xFFFFFFFFu, mx, o));
            if (l == 0) red[w] = mx;
            __syncthreads();
            const float Bv = fmaxf(fmaxf(red[0], red[1]), fmaxf(red[2], red[3]));
            float s = 0.f;
#pragma unroll 4
            for (int e = 0; e < rcnt; ++e) {
                float t  = rtp[e * ES];
                int  idx = rip[e * ES];
                s += ex2f(sh[idx] + (t - Bv));
            }
            g_uK[gi] = logmu - (Bv - rminK + lg2f(s));
            __threadfence();
            asm volatile("barrier.cluster.arrive.aligned;" ::: "memory");
            asm volatile("barrier.cluster.wait.aligned;"   ::: "memory");
        }
    }
}

// ------------------------------- final -----------------------------------
__global__ void __launch_bounds__(256) finalpass(const float* __restrict__ C,
                                                 float* __restrict__ pi) {
    const int n = blockIdx.y, ib = blockIdx.x;
    __shared__ float vsK[PP];
    __shared__ float usr[16];
    __shared__ float red[256];
    const int tid = threadIdx.x;

    for (int j = tid; j < PP; j += 256) vsK[j] = g_vK[n * PP + j];
    if (tid < 16) usr[tid] = g_uK[n * PP + ib * 16 + tid];
    __syncthreads();

    const float4* Cb = (const float4*)(C + ((size_t)n << 20) + (size_t)ib * 16 * PP);
    float4* Pb = pi ? (float4*)(pi + ((size_t)n << 20) + (size_t)ib * 16 * PP) : nullptr;
    const float4* vs4 = (const float4*)vsK;

    float acc = 0.f;
#pragma unroll 4
    for (int e = tid; e < 4096; e += 256) {
        int row = e >> 8;
        int c4  = e & 255;
        float uK = usr[row];
        float4 c  = Cb[e];
        float4 vv = vs4[c4];
        float p0 = ex2f(fmaf(c.x, NKLOG, uK + vv.x));
        float p1 = ex2f(fmaf(c.y, NKLOG, uK + vv.y));
        float p2 = ex2f(fmaf(c.z, NKLOG, uK + vv.z));
        float p3 = ex2f(fmaf(c.w, NKLOG, uK + vv.w));
        acc = fmaf(p0, c.x, acc);
        acc = fmaf(p1, c.y, acc);
        acc = fmaf(p2, c.z, acc);
        acc = fmaf(p3, c.w, acc);
        if (Pb) Pb[e] = make_float4(p0, p1, p2, p3);
    }

    red[tid] = acc;
    __syncthreads();
#pragma unroll
    for (int st = 128; st; st >>= 1) {
        if (tid < st) red[tid] += red[tid + st];
        __syncthreads();
    }
    if (tid == 0) g_part[n * 64 + ib] = red[0];
}

__global__ void costred(float* __restrict__ cost) {
    int n = threadIdx.x;
    if (n < NB) {
        float s = 0.f;
#pragma unroll
        for (int k = 0; k < 64; ++k) s += g_part[n * 64 + k];
        if (cost) cost[n] = s;
        else      g_cost[n] = s;
    }
}

extern "C" void kernel_launch(void* const* d_in, const int* in_sizes, int n_in,
                              void* d_out, int out_size) {
    // C is the largest input; the remaining two are mu, nu in order.
    int ci = 0;
    for (int k = 1; k < n_in; ++k) if (in_sizes[k] > in_sizes[ci]) ci = k;
    const float* in2[2]; int w = 0;
    for (int k = 0; k < n_in && w < 2; ++k) if (k != ci) in2[w++] = (const float*)d_in[k];
    const float* mu = in2[0];
    const float* nu = in2[1];
    const float* C  = (const float*)d_in[ci];

    float* out = (float*)d_out;
    float* cost = nullptr;
    float* pi   = nullptr;
    const int NPI = NB * PP * PP;
    if (out_size >= NPI + NB)      { cost = out;     pi = out + NB; }
    else if (out_size == NPI)      { cost = nullptr; pi = out; }
    else                           { cost = out;     pi = nullptr; }

    init_k<<<(NB * PP + 255) / 256, 256>>>(mu, nu);
    pad_k<<<(CAP * NB * PP + 255) / 256, 256>>>();
    colmin_k<<<dim3(16, 16), 256>>>(C);
    colcnt_k<<<dim3(32, 16), 256>>>(C);
    colscan_k<<<64, 256>>>();
    colwrite_k<<<dim3(32, 16), 256>>>(C);
    rowmincompact_k<<<dim3(128, 16), 256>>>(C);

    iter_k<<<dim3(8, 16), 128>>>();

    finalpass<<<dim3(64, 16), 256>>>(C, pi);
    costred<<<1, 32>>>(cost);
}

// round 11
// speedup vs baseline: 1.0797x; 1.0797x over previous
#include <cuda_runtime.h>
#include <math.h>

#define NB 16
#define PP 1024
#define CAP 96
#define TSEL 0.045f
#define ES (NB * PP)   /* e-plane stride (elements) in sparse tables */

static constexpr float KLOG  = 1442.6950408889634f;   // 1/(EPS*ln2)
static constexpr float NKLOG = -1442.6950408889634f;
static constexpr float LGEPS = 1e-8f;

// Persistent scratch (module globals; no runtime allocation)
__device__ float g_uK[NB * PP];
__device__ float g_vK[NB * PP];
__device__ float g_logmu2[NB * PP];
__device__ float g_lognu2[NB * PP];
__device__ float g_cmin[NB * PP];
__device__ float g_cminK[NB * PP];
__device__ float g_rminK[NB * PP];
__device__ uint2 g_cte[CAP * NB * PP];   // packed {t=(min-C)*K, row idx}, [e][n][j]
__device__ uint2 g_rte[CAP * NB * PP];   // packed {t, col idx},            [e][n][i]
__device__ int   g_ccnt[NB * PP];
__device__ int   g_rcnt[NB * PP];
__device__ int   g_ccnt8[NB * 8 * PP];
__device__ int   g_coff8[NB * 8 * PP];
__device__ float g_part[NB * 64];
__device__ float g_cost[NB];

__device__ __forceinline__ float ex2f(float x) {
    float y; asm("ex2.approx.ftz.f32 %0, %1;" : "=f"(y) : "f"(x)); return y;
}
__device__ __forceinline__ float lg2f(float x) {
    float y; asm("lg2.approx.ftz.f32 %0, %1;" : "=f"(y) : "f"(x)); return y;
}

__global__ void __launch_bounds__(256) init_k(const float* __restrict__ mu,
                                              const float* __restrict__ nu) {
    int t = blockIdx.x * blockDim.x + threadIdx.x;
    if (t < NB * PP) {
        g_logmu2[t] = log2f(mu[t] + LGEPS);
        g_lognu2[t] = log2f(nu[t] + LGEPS);
    }
}

// Prefill sparse tables so padded entries contribute exactly 0 (ex2(-1e9)->0, FTZ).
__global__ void __launch_bounds__(256) pad_k() {
    int t = blockIdx.x * blockDim.x + threadIdx.x;
    if (t < CAP * NB * PP) {
        uint2 p; p.x = __float_as_uint(-1e9f); p.y = 0;
        g_cte[t] = p; g_rte[t] = p;
    }
}

// ------------------------- per-column min -------------------------
__global__ void __launch_bounds__(256) colmin_k(const float* __restrict__ C) {
    const int n = blockIdx.y, cb = blockIdx.x;
    __shared__ float pm[16 * 64];
    const int tid = threadIdx.x;
    const int cg = tid & 15, rg = tid >> 4;
    const float4* Cp = (const float4*)(C + ((size_t)n << 20)
                       + (size_t)(rg * 64) * PP) + cb * 16 + cg;
    float4 mn = make_float4(1e30f, 1e30f, 1e30f, 1e30f);
#pragma unroll 8
    for (int r = 0; r < 64; ++r) {
        float4 c = Cp[r * (PP / 4)];
        mn.x = fminf(mn.x, c.x); mn.y = fminf(mn.y, c.y);
        mn.z = fminf(mn.z, c.z); mn.w = fminf(mn.w, c.w);
    }
    *(float4*)(pm + rg * 64 + cg * 4) = mn;
    __syncthreads();
    if (tid < 64) {
        float m = pm[tid];
#pragma unroll
        for (int k = 1; k < 16; ++k) m = fminf(m, pm[k * 64 + tid]);
        g_cmin[n * PP + cb * 64 + tid]  = m;
        g_cminK[n * PP + cb * 64 + tid] = KLOG * m;
    }
}

// ---------------- column compaction: count / scan / write ----------------
__global__ void __launch_bounds__(256) colcnt_k(const float* __restrict__ C) {
    const int n = blockIdx.y;
    const int w = blockIdx.x * 256 + threadIdx.x;   // 0..8191
    const int q = w >> 10, j = w & 1023;
    const float th = g_cmin[n * PP + j] + TSEL;
    const float* Cp = C + ((size_t)n << 20) + (size_t)(q * 128) * PP + j;
    int cnt = 0;
#pragma unroll 8
    for (int r = 0; r < 128; ++r) cnt += (Cp[(size_t)r * PP] < th) ? 1 : 0;
    g_ccnt8[(n * 8 + q) * PP + j] = cnt;
}

__global__ void __launch_bounds__(256) colscan_k() {
    int t = blockIdx.x * 256 + threadIdx.x;   // 0..16383
    int n = t >> 10, j = t & 1023;
    int off = 0;
#pragma unroll
    for (int q = 0; q < 8; ++q) {
        g_coff8[(n * 8 + q) * PP + j] = off;
        off += g_ccnt8[(n * 8 + q) * PP + j];
    }
    g_ccnt[n * PP + j] = off < CAP ? off : CAP;
}

__global__ void __launch_bounds__(256) colwrite_k(const float* __restrict__ C) {
    const int n = blockIdx.y;
    const int w = blockIdx.x * 256 + threadIdx.x;
    const int q = w >> 10, j = w & 1023;
    const float mn = g_cmin[n * PP + j];
    const float th = mn + TSEL;
    const float* Cp = C + ((size_t)n << 20) + (size_t)(q * 128) * PP + j;
    int e = g_coff8[(n * 8 + q) * PP + j];
    for (int r = 0; r < 128; ++r) {
        float c = Cp[(size_t)r * PP];
        if (c < th) {
            if (e < CAP) {
                uint2 p;
                p.x = __float_as_uint((mn - c) * KLOG);
                p.y = (unsigned)(q * 128 + r);
                g_cte[e * ES + n * PP + j] = p;
            }
            ++e;
        }
    }
}

// ---------------- fused row min + compaction (warp per row) ----------------
__global__ void __launch_bounds__(256) rowmincompact_k(const float* __restrict__ C) {
    const int n = blockIdx.y;
    const int tid = threadIdx.x, w = tid >> 5, l = tid & 31;
    const int i = blockIdx.x * 8 + w;
    const float* Cr = C + ((size_t)n << 20) + (size_t)i * PP;
    const float4* Cr4 = (const float4*)Cr;
    float m = 1e30f;
#pragma unroll
    for (int k = 0; k < 8; ++k) {
        float4 c = Cr4[l + 32 * k];
        m = fminf(m, fminf(fminf(c.x, c.y), fminf(c.z, c.w)));
    }
#pragma unroll
    for (int o = 16; o; o >>= 1) m = fminf(m, __shfl_xor_sync(0xFFFFFFFFu, m, o));
    if (l == 0) g_rminK[n * PP + i] = KLOG * m;

    const float th = m + TSEL;
    int base = 0;
    for (int cb = 0; cb < 32; ++cb) {
        float c = Cr[cb * 32 + l];
        bool p = c < th;
        unsigned msk = __ballot_sync(0xFFFFFFFFu, p);
        int e = base + __popc(msk & ((1u << l) - 1u));
        if (p && e < CAP) {
            uint2 pk;
            pk.x = __float_as_uint((m - c) * KLOG);
            pk.y = (unsigned)(cb * 32 + l);
            g_rte[e * ES + n * PP + i] = pk;
        }
        base += __popc(msk);
    }
    if (l == 0) g_rcnt[n * PP + i] = base < CAP ? base : CAP;
}

// ---------------------------------------------------------------------------
// Persistent iteration: ONE CTA per batch (16 CTAs x 1024 threads).
// u and v live in SMEM for all 100 iterations; only __syncthreads between
// phases. Thread t owns column t (col phase) and row t (row phase).
// ---------------------------------------------------------------------------
__global__ void __launch_bounds__(1024) iter_k() {
    const int n   = blockIdx.x;
    const int tid = threadIdx.x;
    const int gi  = n * PP + tid;
    __shared__ float su[PP];
    __shared__ float sv[PP];
    __shared__ float red[32];
    const int w = tid >> 5, l = tid & 31;

    const float cminK = g_cminK[gi];
    const float lognu = g_lognu2[gi];
    const float rminK = g_rminK[gi];
    const float logmu = g_logmu2[gi];
    int ccnt = g_ccnt[gi], rcnt = g_rcnt[gi];
#pragma unroll
    for (int o = 16; o; o >>= 1) {
        ccnt = max(ccnt, __shfl_xor_sync(0xFFFFFFFFu, ccnt, o));
        rcnt = max(rcnt, __shfl_xor_sync(0xFFFFFFFFu, rcnt, o));
    }
    const uint2* ctp = g_cte + n * PP + tid;
    const uint2* rtp = g_rte + n * PP + tid;

    su[tid] = KLOG;          // u = 1  ->  uK = K
    float Bu = KLOG;         // exact max of su
    float Bv = 0.f;
    __syncthreads();

    for (int it = 0; it < 100; ++it) {
        // -------- col phase: v_tid from su --------
        {
            float s = 0.f;
#pragma unroll 4
            for (int e = 0; e < ccnt; ++e) {
                uint2 p = ctp[e * ES];
                float t = __uint_as_float(p.x);
                s += ex2f(su[p.y] + (t - Bu));
            }
            float d = lognu - (Bu - cminK + lg2f(s));
            sv[tid] = d;
            float mx = d;
#pragma unroll
            for (int o = 16; o; o >>= 1) mx = fmaxf(mx, __shfl_xor_sync(0xFFFFFFFFu, mx, o));
            if (l == 0) red[w] = mx;
            __syncthreads();
            if (tid < 32) {
                float m = red[tid];
#pragma unroll
                for (int o = 16; o; o >>= 1) m = fmaxf(m, __shfl_xor_sync(0xFFFFFFFFu, m, o));
                if (tid == 0) red[0] = m;
            }
            __syncthreads();
            Bv = red[0];
        }
        // -------- row phase: u_tid from sv --------
        {
            float s = 0.f;
#pragma unroll 4
            for (int e = 0; e < rcnt; ++e) {
                uint2 p = rtp[e * ES];
                float t = __uint_as_float(p.x);
                s += ex2f(sv[p.y] + (t - Bv));
            }
            float d = logmu - (Bv - rminK + lg2f(s));
            su[tid] = d;
            float mx = d;
#pragma unroll
            for (int o = 16; o; o >>= 1) mx = fmaxf(mx, __shfl_xor_sync(0xFFFFFFFFu, mx, o));
            if (l == 0) red[w] = mx;
            __syncthreads();
            if (tid < 32) {
                float m = red[tid];
#pragma unroll
                for (int o = 16; o; o >>= 1) m = fmaxf(m, __shfl_xor_sync(0xFFFFFFFFu, m, o));
                if (tid == 0) red[0] = m;
            }
            __syncthreads();
            Bu = red[0];
        }
    }

    g_uK[gi] = su[tid];
    g_vK[gi] = sv[tid];
}

// ------------------------------- final -----------------------------------
__global__ void __launch_bounds__(256) finalpass(const float* __restrict__ C,
                                                 float* __restrict__ pi) {
    const int n = blockIdx.y, ib = blockIdx.x;
    __shared__ float vsK[PP];
    __shared__ float usr[16];
    __shared__ float red[256];
    const int tid = threadIdx.x;

    for (int j = tid; j < PP; j += 256) vsK[j] = g_vK[n * PP + j];
    if (tid < 16) usr[tid] = g_uK[n * PP + ib * 16 + tid];
    __syncthreads();

    const float4* Cb = (const float4*)(C + ((size_t)n << 20) + (size_t)ib * 16 * PP);
    float4* Pb = pi ? (float4*)(pi + ((size_t)n << 20) + (size_t)ib * 16 * PP) : nullptr;
    const float4* vs4 = (const float4*)vsK;

    float acc = 0.f;
#pragma unroll 4
    for (int e = tid; e < 4096; e += 256) {
        int row = e >> 8;
        int c4  = e & 255;
        float uK = usr[row];
        float4 c  = Cb[e];
        float4 vv = vs4[c4];
        float p0 = ex2f(fmaf(c.x, NKLOG, uK + vv.x));
        float p1 = ex2f(fmaf(c.y, NKLOG, uK + vv.y));
        float p2 = ex2f(fmaf(c.z, NKLOG, uK + vv.z));
        float p3 = ex2f(fmaf(c.w, NKLOG, uK + vv.w));
        acc = fmaf(p0, c.x, acc);
        acc = fmaf(p1, c.y, acc);
        acc = fmaf(p2, c.z, acc);
        acc = fmaf(p3, c.w, acc);
        if (Pb) Pb[e] = make_float4(p0, p1, p2, p3);
    }

    red[tid] = acc;
    __syncthreads();
#pragma unroll
    for (int st = 128; st; st >>= 1) {
        if (tid < st) red[tid] += red[tid + st];
        __syncthreads();
    }
    if (tid == 0) g_part[n * 64 + ib] = red[0];
}

__global__ void costred(float* __restrict__ cost) {
    int n = threadIdx.x;
    if (n < NB) {
        float s = 0.f;
#pragma unroll
        for (int k = 0; k < 64; ++k) s += g_part[n * 64 + k];
        if (cost) cost[n] = s;
        else      g_cost[n] = s;
    }
}

extern "C" void kernel_launch(void* const* d_in, const int* in_sizes, int n_in,
                              void* d_out, int out_size) {
    // C is the largest input; the remaining two are mu, nu in order.
    int ci = 0;
    for (int k = 1; k < n_in; ++k) if (in_sizes[k] > in_sizes[ci]) ci = k;
    const float* in2[2]; int w = 0;
    for (int k = 0; k < n_in && w < 2; ++k) if (k != ci) in2[w++] = (const float*)d_in[k];
    const float* mu = in2[0];
    const float* nu = in2[1];
    const float* C  = (const float*)d_in[ci];

    float* out = (float*)d_out;
    float* cost = nullptr;
    float* pi   = nullptr;
    const int NPI = NB * PP * PP;
    if (out_size >= NPI + NB)      { cost = out;     pi = out + NB; }
    else if (out_size == NPI)      { cost = nullptr; pi = out; }
    else                           { cost = out;     pi = nullptr; }

    init_k<<<(NB * PP + 255) / 256, 256>>>(mu, nu);
    pad_k<<<(CAP * NB * PP + 255) / 256, 256>>>();
    colmin_k<<<dim3(16, 16), 256>>>(C);
    colcnt_k<<<dim3(32, 16), 256>>>(C);
    colscan_k<<<64, 256>>>();
    colwrite_k<<<dim3(32, 16), 256>>>(C);
    rowmincompact_k<<<dim3(128, 16), 256>>>(C);

    iter_k<<<16, 1024>>>();

    finalpass<<<dim3(64, 16), 256>>>(C, pi);
    costred<<<1, 32>>>(cost);
}

// round 13
// speedup vs baseline: 2.6159x; 2.4228x over previous
#include <cuda_runtime.h>
#include <math.h>

#define NB 16
#define PP 1024
#define CAP 96
#define TSEL 0.045f
#define ES (NB * PP)   /* e-plane stride (elements) in sparse tables */

static constexpr float KLOG  = 1442.6950408889634f;   // 1/(EPS*ln2)
static constexpr float NKLOG = -1442.6950408889634f;
static constexpr float LGEPS = 1e-8f;

// Persistent scratch (module globals; no runtime allocation)
__device__ float g_uK[NB * PP];
__device__ float g_vK[NB * PP];
__device__ float g_logmu2[NB * PP];
__device__ float g_lognu2[NB * PP];
__device__ float g_cmin[NB * PP];
__device__ float g_cminK[NB * PP];
__device__ float g_rminK[NB * PP];
__device__ uint2 g_cte[CAP * NB * PP];   // packed {t=(min-C)*K, row idx}, [e][n][j]
__device__ uint2 g_rte[CAP * NB * PP];   // packed {t, col idx},            [e][n][i]
__device__ int   g_ccnt[NB * PP];
__device__ int   g_rcnt[NB * PP];
__device__ int   g_ccnt8[NB * 8 * PP];
__device__ int   g_coff8[NB * 8 * PP];
__device__ float g_part[NB * 64];
__device__ float g_cost[NB];

__device__ __forceinline__ float ex2f(float x) {
    float y; asm("ex2.approx.ftz.f32 %0, %1;" : "=f"(y) : "f"(x)); return y;
}
__device__ __forceinline__ float lg2f(float x) {
    float y; asm("lg2.approx.ftz.f32 %0, %1;" : "=f"(y) : "f"(x)); return y;
}

__global__ void __launch_bounds__(256) init_k(const float* __restrict__ mu,
                                              const float* __restrict__ nu) {
    int t = blockIdx.x * blockDim.x + threadIdx.x;
    if (t < NB * PP) {
        g_logmu2[t] = log2f(mu[t] + LGEPS);
        g_lognu2[t] = log2f(nu[t] + LGEPS);
        g_uK[t] = KLOG;   // u = 1
    }
}

// Prefill sparse tables so padded entries contribute exactly 0 (ex2(-1e9)->0, FTZ).
__global__ void __launch_bounds__(256) pad_k() {
    int t = blockIdx.x * blockDim.x + threadIdx.x;
    if (t < CAP * NB * PP) {
        uint2 p; p.x = __float_as_uint(-1e9f); p.y = 0;
        g_cte[t] = p; g_rte[t] = p;
    }
}

// ------------------------- per-column min -------------------------
__global__ void __launch_bounds__(256) colmin_k(const float* __restrict__ C) {
    const int n = blockIdx.y, cb = blockIdx.x;
    __shared__ float pm[16 * 64];
    const int tid = threadIdx.x;
    const int cg = tid & 15, rg = tid >> 4;
    const float4* Cp = (const float4*)(C + ((size_t)n << 20)
                       + (size_t)(rg * 64) * PP) + cb * 16 + cg;
    float4 mn = make_float4(1e30f, 1e30f, 1e30f, 1e30f);
#pragma unroll 8
    for (int r = 0; r < 64; ++r) {
        float4 c = Cp[r * (PP / 4)];
        mn.x = fminf(mn.x, c.x); mn.y = fminf(mn.y, c.y);
        mn.z = fminf(mn.z, c.z); mn.w = fminf(mn.w, c.w);
    }
    *(float4*)(pm + rg * 64 + cg * 4) = mn;
    __syncthreads();
    if (tid < 64) {
        float m = pm[tid];
#pragma unroll
        for (int k = 1; k < 16; ++k) m = fminf(m, pm[k * 64 + tid]);
        g_cmin[n * PP + cb * 64 + tid]  = m;
        g_cminK[n * PP + cb * 64 + tid] = KLOG * m;
    }
}

// ---------------- column compaction: count / scan / write ----------------
__global__ void __launch_bounds__(256) colcnt_k(const float* __restrict__ C) {
    const int n = blockIdx.y;
    const int w = blockIdx.x * 256 + threadIdx.x;   // 0..8191
    const int q = w >> 10, j = w & 1023;
    const float th = g_cmin[n * PP + j] + TSEL;
    const float* Cp = C + ((size_t)n << 20) + (size_t)(q * 128) * PP + j;
    int cnt = 0;
#pragma unroll 8
    for (int r = 0; r < 128; ++r) cnt += (Cp[(size_t)r * PP] < th) ? 1 : 0;
    g_ccnt8[(n * 8 + q) * PP + j] = cnt;
}

__global__ void __launch_bounds__(256) colscan_k() {
    int t = blockIdx.x * 256 + threadIdx.x;   // 0..16383
    int n = t >> 10, j = t & 1023;
    int off = 0;
#pragma unroll
    for (int q = 0; q < 8; ++q) {
        g_coff8[(n * 8 + q) * PP + j] = off;
        off += g_ccnt8[(n * 8 + q) * PP + j];
    }
    g_ccnt[n * PP + j] = off < CAP ? off : CAP;
}

__global__ void __launch_bounds__(256) colwrite_k(const float* __restrict__ C) {
    const int n = blockIdx.y;
    const int w = blockIdx.x * 256 + threadIdx.x;
    const int q = w >> 10, j = w & 1023;
    const float mn = g_cmin[n * PP + j];
    const float th = mn + TSEL;
    const float* Cp = C + ((size_t)n << 20) + (size_t)(q * 128) * PP + j;
    int e = g_coff8[(n * 8 + q) * PP + j];
    for (int r = 0; r < 128; ++r) {
        float c = Cp[(size_t)r * PP];
        if (c < th) {
            if (e < CAP) {
                uint2 p;
                p.x = __float_as_uint((mn - c) * KLOG);
                p.y = (unsigned)(q * 128 + r);
                g_cte[e * ES + n * PP + j] = p;
            }
            ++e;
        }
    }
}

// ---------------- fused row min + compaction (warp per row) ----------------
__global__ void __launch_bounds__(256) rowmincompact_k(const float* __restrict__ C) {
    const int n = blockIdx.y;
    const int tid = threadIdx.x, w = tid >> 5, l = tid & 31;
    const int i = blockIdx.x * 8 + w;
    const float* Cr = C + ((size_t)n << 20) + (size_t)i * PP;
    const float4* Cr4 = (const float4*)Cr;
    float m = 1e30f;
#pragma unroll
    for (int k = 0; k < 8; ++k) {
        float4 c = Cr4[l + 32 * k];
        m = fminf(m, fminf(fminf(c.x, c.y), fminf(c.z, c.w)));
    }
#pragma unroll
    for (int o = 16; o; o >>= 1) m = fminf(m, __shfl_xor_sync(0xFFFFFFFFu, m, o));
    if (l == 0) g_rminK[n * PP + i] = KLOG * m;

    const float th = m + TSEL;
    int base = 0;
    for (int cb = 0; cb < 32; ++cb) {
        float c = Cr[cb * 32 + l];
        bool p = c < th;
        unsigned msk = __ballot_sync(0xFFFFFFFFu, p);
        int e = base + __popc(msk & ((1u << l) - 1u));
        if (p && e < CAP) {
            uint2 pk;
            pk.x = __float_as_uint((m - c) * KLOG);
            pk.y = (unsigned)(cb * 32 + l);
            g_rte[e * ES + n * PP + i] = pk;
        }
        base += __popc(msk);
    }
    if (l == 0) g_rcnt[n * PP + i] = base < CAP ? base : CAP;
}

// ---------------------------------------------------------------------------
// Persistent iteration: cluster of 8 CTAs per batch, 256 threads per CTA.
// Thread pair (t, t+128) splits one output's entry list (even/odd e).
// Sync = barrier.cluster only: arrive has RELEASE and wait has ACQUIRE
// semantics at cluster scope (PTX defaults), which orders the plain dual
// stores against peers. Dual reads use .cv (L2-direct) so freshness never
// depends on L1 invalidation behavior. No fences anywhere.
// ---------------------------------------------------------------------------
__global__ void __launch_bounds__(256) __cluster_dims__(8, 1, 1)
iter_k() {
    const int n   = blockIdx.y;
    const int c   = blockIdx.x;
    const int tid = threadIdx.x;
    const int tl  = tid & 127;          // owned output within CTA block
    const int hi  = tid >> 7;           // 0 = even entries, 1 = odd entries
    const int j   = c * 128 + tl;       // owned col (col phase) / row (row phase)
    const int gi  = n * PP + j;
    __shared__ float sh[PP];
    __shared__ float ss[128];
    __shared__ float rmax[8];
    const int w = tid >> 5, l = tid & 31;

    const float cminK = g_cminK[gi];
    const float lognu = g_lognu2[gi];
    const float rminK = g_rminK[gi];
    const float logmu = g_logmu2[gi];
    int ccnt = g_ccnt[gi], rcnt = g_rcnt[gi];
#pragma unroll
    for (int o = 16; o; o >>= 1) {
        ccnt = max(ccnt, __shfl_xor_sync(0xFFFFFFFFu, ccnt, o));
        rcnt = max(rcnt, __shfl_xor_sync(0xFFFFFFFFu, rcnt, o));
    }
    const int cK = (ccnt + 1 - hi) >> 1;   // entries this thread handles
    const int rK = (rcnt + 1 - hi) >> 1;
    const uint2* ctp = g_cte + (size_t)hi * ES + gi;   // start e = hi, step 2
    const uint2* rtp = g_rte + (size_t)hi * ES + gi;
    float* uKp = g_uK + n * PP;
    float* vKp = g_vK + n * PP;
    float4* sh4 = (float4*)sh;

    for (int it = 0; it < 100; ++it) {
        // ---------------- col phase: all u -> v_j ----------------
        {
            float4 a = __ldcv((const float4*)uKp + tid);
            sh4[tid] = a;
            float mx = fmaxf(fmaxf(a.x, a.y), fmaxf(a.z, a.w));
#pragma unroll
            for (int o = 16; o; o >>= 1) mx = fmaxf(mx, __shfl_xor_sync(0xFFFFFFFFu, mx, o));
            if (l == 0) rmax[w] = mx;
            __syncthreads();
            float B = rmax[0];
#pragma unroll
            for (int k = 1; k < 8; ++k) B = fmaxf(B, rmax[k]);
            float s = 0.f;
#pragma unroll 4
            for (int e = 0; e < cK; ++e) {
                uint2 p = ctp[(size_t)(2 * e) * ES];
                s += ex2f((sh[p.y] - B) + __uint_as_float(p.x));
            }
            if (hi) ss[tl] = s;
            __syncthreads();
            if (!hi) {
                float st = s + ss[tl];
                vKp[j] = lognu - (B - cminK + lg2f(st));
            }
            asm volatile("barrier.cluster.arrive.aligned;" ::: "memory");
            asm volatile("barrier.cluster.wait.aligned;"   ::: "memory");
        }
        // ---------------- row phase: all v -> u_i ----------------
        {
            float4 a = __ldcv((const float4*)vKp + tid);
            sh4[tid] = a;
            float mx = fmaxf(fmaxf(a.x, a.y), fmaxf(a.z, a.w));
#pragma unroll
            for (int o = 16; o; o >>= 1) mx = fmaxf(mx, __shfl_xor_sync(0xFFFFFFFFu, mx, o));
            if (l == 0) rmax[w] = mx;
            __syncthreads();
            float B = rmax[0];
#pragma unroll
            for (int k = 1; k < 8; ++k) B = fmaxf(B, rmax[k]);
            float s = 0.f;
#pragma unroll 4
            for (int e = 0; e < rK; ++e) {
                uint2 p = rtp[(size_t)(2 * e) * ES];
                s += ex2f((sh[p.y] - B) + __uint_as_float(p.x));
            }
            if (hi) ss[tl] = s;
            __syncthreads();
            if (!hi) {
                float st = s + ss[tl];
                uKp[j] = logmu - (B - rminK + lg2f(st));
            }
            if (it == 99) break;   // kernel boundary publishes final u
            asm volatile("barrier.cluster.arrive.aligned;" ::: "memory");
            asm volatile("barrier.cluster.wait.aligned;"   ::: "memory");
        }
    }
}

// ------------------------------- final -----------------------------------
__global__ void __launch_bounds__(256) finalpass(const float* __restrict__ C,
                                                 float* __restrict__ pi) {
    const int n = blockIdx.y, ib = blockIdx.x;
    __shared__ float vsK[PP];
    __shared__ float usr[16];
    __shared__ float red[256];
    const int tid = threadIdx.x;

    for (int j = tid; j < PP; j += 256) vsK[j] = g_vK[n * PP + j];
    if (tid < 16) usr[tid] = g_uK[n * PP + ib * 16 + tid];
    __syncthreads();

    const float4* Cb = (const float4*)(C + ((size_t)n << 20) + (size_t)ib * 16 * PP);
    float4* Pb = pi ? (float4*)(pi + ((size_t)n << 20) + (size_t)ib * 16 * PP) : nullptr;
    const float4* vs4 = (const float4*)vsK;

    float acc = 0.f;
#pragma unroll 4
    for (int e = tid; e < 4096; e += 256) {
        int row = e >> 8;
        int c4  = e & 255;
        float uK = usr[row];
        float4 c  = Cb[e];
        float4 vv = vs4[c4];
        float p0 = ex2f(fmaf(c.x, NKLOG, uK + vv.x));
        float p1 = ex2f(fmaf(c.y, NKLOG, uK + vv.y));
        float p2 = ex2f(fmaf(c.z, NKLOG, uK + vv.z));
        float p3 = ex2f(fmaf(c.w, NKLOG, uK + vv.w));
        acc = fmaf(p0, c.x, acc);
        acc = fmaf(p1, c.y, acc);
        acc = fmaf(p2, c.z, acc);
        acc = fmaf(p3, c.w, acc);
        if (Pb) Pb[e] = make_float4(p0, p1, p2, p3);
    }

    red[tid] = acc;
    __syncthreads();
#pragma unroll
    for (int st = 128; st; st >>= 1) {
        if (tid < st) red[tid] += red[tid + st];
        __syncthreads();
    }
    if (tid == 0) g_part[n * 64 + ib] = red[0];
}

__global__ void costred(float* __restrict__ cost) {
    int n = threadIdx.x;
    if (n < NB) {
        float s = 0.f;
#pragma unroll
        for (int k = 0; k < 64; ++k) s += g_part[n * 64 + k];
        if (cost) cost[n] = s;
        else      g_cost[n] = s;
    }
}

extern "C" void kernel_launch(void* const* d_in, const int* in_sizes, int n_in,
                              void* d_out, int out_size) {
    // C is the largest input; the remaining two are mu, nu in order.
    int ci = 0;
    for (int k = 1; k < n_in; ++k) if (in_sizes[k] > in_sizes[ci]) ci = k;
    const float* in2[2]; int w = 0;
    for (int k = 0; k < n_in && w < 2; ++k) if (k != ci) in2[w++] = (const float*)d_in[k];
    const float* mu = in2[0];
    const float* nu = in2[1];
    const float* C  = (const float*)d_in[ci];

    float* out = (float*)d_out;
    float* cost = nullptr;
    float* pi   = nullptr;
    const int NPI = NB * PP * PP;
    if (out_size >= NPI + NB)      { cost = out;     pi = out + NB; }
    else if (out_size == NPI)      { cost = nullptr; pi = out; }
    else                           { cost = out;     pi = nullptr; }

    init_k<<<(NB * PP + 255) / 256, 256>>>(mu, nu);
    pad_k<<<(CAP * NB * PP + 255) / 256, 256>>>();
    colmin_k<<<dim3(16, 16), 256>>>(C);
    colcnt_k<<<dim3(32, 16), 256>>>(C);
    colscan_k<<<64, 256>>>();
    colwrite_k<<<dim3(32, 16), 256>>>(C);
    rowmincompact_k<<<dim3(128, 16), 256>>>(C);

    iter_k<<<dim3(8, 16), 256>>>();

    finalpass<<<dim3(64, 16), 256>>>(C, pi);
    costred<<<1, 32>>>(cost);
}

// round 15
// speedup vs baseline: 2.9658x; 1.1338x over previous
#include <cuda_runtime.h>
#include <math.h>
#include <cstdint>

#define NB 16
#define PP 1024
#define CAP 96
#define TSEL 0.045f
#define ES (NB * PP)   /* e-plane stride (elements) in sparse tables */

static constexpr float KLOG  = 1442.6950408889634f;   // 1/(EPS*ln2)
static constexpr float NKLOG = -1442.6950408889634f;
static constexpr float LGEPS = 1e-8f;

// Persistent scratch (module globals; no runtime allocation)
__device__ float g_uK[NB * PP];
__device__ float g_vK[NB * PP];
__device__ float g_logmu2[NB * PP];
__device__ float g_lognu2[NB * PP];
__device__ float g_cmin[NB * PP];
__device__ float g_cminK[NB * PP];
__device__ float g_rminK[NB * PP];
__device__ uint2 g_cte[CAP * NB * PP];   // packed {t=(min-C)*K, row idx}, [e][n][j]
__device__ uint2 g_rte[CAP * NB * PP];   // packed {t, col idx},            [e][n][i]
__device__ int   g_ccnt[NB * PP];
__device__ int   g_rcnt[NB * PP];
__device__ int   g_ccnt8[NB * 8 * PP];
__device__ int   g_coff8[NB * 8 * PP];
__device__ float g_part[NB * 64];
__device__ float g_cost[NB];

__device__ __forceinline__ float ex2f(float x) {
    float y; asm("ex2.approx.ftz.f32 %0, %1;" : "=f"(y) : "f"(x)); return y;
}
__device__ __forceinline__ float lg2f(float x) {
    float y; asm("lg2.approx.ftz.f32 %0, %1;" : "=f"(y) : "f"(x)); return y;
}

__device__ __forceinline__ unsigned int smem_u32(const void* p) {
    unsigned int a;
    asm("{ .reg .u64 t; cvta.to.shared.u64 t, %1; cvt.u32.u64 %0, t; }"
        : "=r"(a) : "l"(p));
    return a;
}

// Arrive on cluster-rank `rank`'s copy of the mbarrier at local smem addr.
// RELEASE at cluster scope: orders this thread's (and, via the preceding
// __syncthreads, the whole CTA's) prior global stores for peers' acquires.
__device__ __forceinline__ void mbar_arrive_peer(unsigned int local_addr, unsigned int rank) {
    unsigned int rem;
    asm volatile("mapa.shared::cluster.u32 %0, %1, %2;"
                 : "=r"(rem) : "r"(local_addr), "r"(rank));
    asm volatile("mbarrier.arrive.release.cluster.shared::cluster.b64 _, [%0];"
                 :: "r"(rem) : "memory");
}

// Spin on local mbarrier phase parity with ACQUIRE at cluster scope.
__device__ __forceinline__ void mbar_wait(unsigned int addr, unsigned int parity) {
    asm volatile(
        "{\n\t"
        ".reg .pred P;\n\t"
        "WL%=:\n\t"
        "mbarrier.try_wait.parity.acquire.cluster.shared::cta.b64 P, [%0], %1;\n\t"
        "@!P bra WL%=;\n\t"
        "}"
        :: "r"(addr), "r"(parity) : "memory");
}

__global__ void __launch_bounds__(256) init_k(const float* __restrict__ mu,
                                              const float* __restrict__ nu) {
    int t = blockIdx.x * blockDim.x + threadIdx.x;
    if (t < NB * PP) {
        g_logmu2[t] = log2f(mu[t] + LGEPS);
        g_lognu2[t] = log2f(nu[t] + LGEPS);
        g_uK[t] = KLOG;   // u = 1
    }
}

// Prefill sparse tables so padded entries contribute exactly 0 (ex2(-1e9)->0, FTZ).
__global__ void __launch_bounds__(256) pad_k() {
    int t = blockIdx.x * blockDim.x + threadIdx.x;
    if (t < CAP * NB * PP) {
        uint2 p; p.x = __float_as_uint(-1e9f); p.y = 0;
        g_cte[t] = p; g_rte[t] = p;
    }
}

// ------------------------- per-column min -------------------------
__global__ void __launch_bounds__(256) colmin_k(const float* __restrict__ C) {
    const int n = blockIdx.y, cb = blockIdx.x;
    __shared__ float pm[16 * 64];
    const int tid = threadIdx.x;
    const int cg = tid & 15, rg = tid >> 4;
    const float4* Cp = (const float4*)(C + ((size_t)n << 20)
                       + (size_t)(rg * 64) * PP) + cb * 16 + cg;
    float4 mn = make_float4(1e30f, 1e30f, 1e30f, 1e30f);
#pragma unroll 8
    for (int r = 0; r < 64; ++r) {
        float4 c = Cp[r * (PP / 4)];
        mn.x = fminf(mn.x, c.x); mn.y = fminf(mn.y, c.y);
        mn.z = fminf(mn.z, c.z); mn.w = fminf(mn.w, c.w);
    }
    *(float4*)(pm + rg * 64 + cg * 4) = mn;
    __syncthreads();
    if (tid < 64) {
        float m = pm[tid];
#pragma unroll
        for (int k = 1; k < 16; ++k) m = fminf(m, pm[k * 64 + tid]);
        g_cmin[n * PP + cb * 64 + tid]  = m;
        g_cminK[n * PP + cb * 64 + tid] = KLOG * m;
    }
}

// ---------------- column compaction: count / scan / write ----------------
__global__ void __launch_bounds__(256) colcnt_k(const float* __restrict__ C) {
    const int n = blockIdx.y;
    const int w = blockIdx.x * 256 + threadIdx.x;   // 0..8191
    const int q = w >> 10, j = w & 1023;
    const float th = g_cmin[n * PP + j] + TSEL;
    const float* Cp = C + ((size_t)n << 20) + (size_t)(q * 128) * PP + j;
    int cnt = 0;
#pragma unroll 8
    for (int r = 0; r < 128; ++r) cnt += (Cp[(size_t)r * PP] < th) ? 1 : 0;
    g_ccnt8[(n * 8 + q) * PP + j] = cnt;
}

__global__ void __launch_bounds__(256) colscan_k() {
    int t = blockIdx.x * 256 + threadIdx.x;   // 0..16383
    int n = t >> 10, j = t & 1023;
    int off = 0;
#pragma unroll
    for (int q = 0; q < 8; ++q) {
        g_coff8[(n * 8 + q) * PP + j] = off;
        off += g_ccnt8[(n * 8 + q) * PP + j];
    }
    g_ccnt[n * PP + j] = off < CAP ? off : CAP;
}

__global__ void __launch_bounds__(256) colwrite_k(const float* __restrict__ C) {
    const int n = blockIdx.y;
    const int w = blockIdx.x * 256 + threadIdx.x;
    const int q = w >> 10, j = w & 1023;
    const float mn = g_cmin[n * PP + j];
    const float th = mn + TSEL;
    const float* Cp = C + ((size_t)n << 20) + (size_t)(q * 128) * PP + j;
    int e = g_coff8[(n * 8 + q) * PP + j];
    for (int r = 0; r < 128; ++r) {
        float c = Cp[(size_t)r * PP];
        if (c < th) {
            if (e < CAP) {
                uint2 p;
                p.x = __float_as_uint((mn - c) * KLOG);
                p.y = (unsigned)(q * 128 + r);
                g_cte[e * ES + n * PP + j] = p;
            }
            ++e;
        }
    }
}

// ---------------- fused row min + compaction (warp per row) ----------------
__global__ void __launch_bounds__(256) rowmincompact_k(const float* __restrict__ C) {
    const int n = blockIdx.y;
    const int tid = threadIdx.x, w = tid >> 5, l = tid & 31;
    const int i = blockIdx.x * 8 + w;
    const float* Cr = C + ((size_t)n << 20) + (size_t)i * PP;
    const float4* Cr4 = (const float4*)Cr;
    float m = 1e30f;
#pragma unroll
    for (int k = 0; k < 8; ++k) {
        float4 c = Cr4[l + 32 * k];
        m = fminf(m, fminf(fminf(c.x, c.y), fminf(c.z, c.w)));
    }
#pragma unroll
    for (int o = 16; o; o >>= 1) m = fminf(m, __shfl_xor_sync(0xFFFFFFFFu, m, o));
    if (l == 0) g_rminK[n * PP + i] = KLOG * m;

    const float th = m + TSEL;
    int base = 0;
    for (int cb = 0; cb < 32; ++cb) {
        float c = Cr[cb * 32 + l];
        bool p = c < th;
        unsigned msk = __ballot_sync(0xFFFFFFFFu, p);
        int e = base + __popc(msk & ((1u << l) - 1u));
        if (p && e < CAP) {
            uint2 pk;
            pk.x = __float_as_uint((m - c) * KLOG);
            pk.y = (unsigned)(cb * 32 + l);
            g_rte[e * ES + n * PP + i] = pk;
        }
        base += __popc(msk);
    }
    if (l == 0) g_rcnt[n * PP + i] = base < CAP ? base : CAP;
}

// ---------------------------------------------------------------------------
// Persistent iteration: cluster of 8 CTAs per batch, 256 threads per CTA.
// Thread pair (t, t+128) splits one output's entry list (even/odd e).
// Sync = DSMEM mbarrier all-to-all: each CTA arrives (release.cluster) on all
// 8 peers' barriers, waits (acquire.cluster) on its own. NO CCTL.IVALL ->
// sparse tables stay L1-resident across all 100 iterations. Dual reads use
// .cv (L2-direct) so freshness never depends on L1 state.
// ---------------------------------------------------------------------------
__global__ void __launch_bounds__(256) __cluster_dims__(8, 1, 1)
iter_k() {
    const int n   = blockIdx.y;
    const int c   = blockIdx.x;
    const int tid = threadIdx.x;
    const int tl  = tid & 127;          // owned output within CTA block
    const int hi  = tid >> 7;           // 0 = even entries, 1 = odd entries
    const int j   = c * 128 + tl;       // owned col (col phase) / row (row phase)
    const int gi  = n * PP + j;
    __shared__ float sh[PP];
    __shared__ float ss[128];
    __shared__ float rmax[8];
    __shared__ __align__(8) unsigned long long mbar;
    const int w = tid >> 5, l = tid & 31;
    const unsigned int mba = smem_u32(&mbar);

    if (tid == 0)
        asm volatile("mbarrier.init.shared.b64 [%0], %1;" :: "r"(mba), "r"(8u) : "memory");
    __syncthreads();
    // One-time cluster barrier: publish mbarrier init before any peer arrives.
    asm volatile("barrier.cluster.arrive.aligned;" ::: "memory");
    asm volatile("barrier.cluster.wait.aligned;"   ::: "memory");

    const float cminK = g_cminK[gi];
    const float lognu = g_lognu2[gi];
    const float rminK = g_rminK[gi];
    const float logmu = g_logmu2[gi];
    int ccnt = g_ccnt[gi], rcnt = g_rcnt[gi];
#pragma unroll
    for (int o = 16; o; o >>= 1) {
        ccnt = max(ccnt, __shfl_xor_sync(0xFFFFFFFFu, ccnt, o));
        rcnt = max(rcnt, __shfl_xor_sync(0xFFFFFFFFu, rcnt, o));
    }
    const int cK = (ccnt + 1 - hi) >> 1;   // entries this thread handles
    const int rK = (rcnt + 1 - hi) >> 1;
    const uint2* ctp = g_cte + (size_t)hi * ES + gi;   // start e = hi, step 2
    const uint2* rtp = g_rte + (size_t)hi * ES + gi;
    float* uKp = g_uK + n * PP;
    float* vKp = g_vK + n * PP;
    float4* sh4 = (float4*)sh;
    unsigned int par = 0;

    for (int it = 0; it < 100; ++it) {
        // ---------------- col phase: all u -> v_j ----------------
        {
            float4 a = __ldcv((const float4*)uKp + tid);
            sh4[tid] = a;
            float mx = fmaxf(fmaxf(a.x, a.y), fmaxf(a.z, a.w));
#pragma unroll
            for (int o = 16; o; o >>= 1) mx = fmaxf(mx, __shfl_xor_sync(0xFFFFFFFFu, mx, o));
            if (l == 0) rmax[w] = mx;
            __syncthreads();
            float B = rmax[0];
#pragma unroll
            for (int k = 1; k < 8; ++k) B = fmaxf(B, rmax[k]);
            float s = 0.f;
#pragma unroll 4
            for (int e = 0; e < cK; ++e) {
                uint2 p = ctp[(size_t)(2 * e) * ES];
                s += ex2f((sh[p.y] - B) + __uint_as_float(p.x));
            }
            if (hi) ss[tl] = s;
            __syncthreads();             // ss visible to low half
            if (!hi) {
                float st = s + ss[tl];
                vKp[j] = lognu - (B - cminK + lg2f(st));
            }
            __syncthreads();             // all v stores issued before arrive
            if (tid < 8) mbar_arrive_peer(mba, (unsigned int)tid);
            mbar_wait(mba, par);
            par ^= 1u;
        }
        // ---------------- row phase: all v -> u_i ----------------
        {
            float4 a = __ldcv((const float4*)vKp + tid);
            sh4[tid] = a;
            float mx = fmaxf(fmaxf(a.x, a.y), fmaxf(a.z, a.w));
#pragma unroll
            for (int o = 16; o; o >>= 1) mx = fmaxf(mx, __shfl_xor_sync(0xFFFFFFFFu, mx, o));
            if (l == 0) rmax[w] = mx;
            __syncthreads();
            float B = rmax[0];
#pragma unroll
            for (int k = 1; k < 8; ++k) B = fmaxf(B, rmax[k]);
            float s = 0.f;
#pragma unroll 4
            for (int e = 0; e < rK; ++e) {
                uint2 p = rtp[(size_t)(2 * e) * ES];
                s += ex2f((sh[p.y] - B) + __uint_as_float(p.x));
            }
            if (hi) ss[tl] = s;
            __syncthreads();
            if (!hi) {
                float st = s + ss[tl];
                uKp[j] = logmu - (B - rminK + lg2f(st));
            }
            if (it == 99) break;         // kernel boundary publishes final u
            __syncthreads();
            if (tid < 8) mbar_arrive_peer(mba, (unsigned int)tid);
            mbar_wait(mba, par);
            par ^= 1u;
        }
    }
}

// ------------------------------- final -----------------------------------
__global__ void __launch_bounds__(256) finalpass(const float* __restrict__ C,
                                                 float* __restrict__ pi) {
    const int n = blockIdx.y, ib = blockIdx.x;
    __shared__ float vsK[PP];
    __shared__ float usr[16];
    __shared__ float red[256];
    const int tid = threadIdx.x;

    for (int j = tid; j < PP; j += 256) vsK[j] = g_vK[n * PP + j];
    if (tid < 16) usr[tid] = g_uK[n * PP + ib * 16 + tid];
    __syncthreads();

    const float4* Cb = (const float4*)(C + ((size_t)n << 20) + (size_t)ib * 16 * PP);
    float4* Pb = pi ? (float4*)(pi + ((size_t)n << 20) + (size_t)ib * 16 * PP) : nullptr;
    const float4* vs4 = (const float4*)vsK;

    float acc = 0.f;
#pragma unroll 4
    for (int e = tid; e < 4096; e += 256) {
        int row = e >> 8;
        int c4  = e & 255;
        float uK = usr[row];
        float4 c  = Cb[e];
        float4 vv = vs4[c4];
        float p0 = ex2f(fmaf(c.x, NKLOG, uK + vv.x));
        float p1 = ex2f(fmaf(c.y, NKLOG, uK + vv.y));
        float p2 = ex2f(fmaf(c.z, NKLOG, uK + vv.z));
        float p3 = ex2f(fmaf(c.w, NKLOG, uK + vv.w));
        acc = fmaf(p0, c.x, acc);
        acc = fmaf(p1, c.y, acc);
        acc = fmaf(p2, c.z, acc);
        acc = fmaf(p3, c.w, acc);
        if (Pb) Pb[e] = make_float4(p0, p1, p2, p3);
    }

    red[tid] = acc;
    __syncthreads();
#pragma unroll
    for (int st = 128; st; st >>= 1) {
        if (tid < st) red[tid] += red[tid + st];
        __syncthreads();
    }
    if (tid == 0) g_part[n * 64 + ib] = red[0];
}

__global__ void costred(float* __restrict__ cost) {
    int n = threadIdx.x;
    if (n < NB) {
        float s = 0.f;
#pragma unroll
        for (int k = 0; k < 64; ++k) s += g_part[n * 64 + k];
        if (cost) cost[n] = s;
        else      g_cost[n] = s;
    }
}

extern "C" void kernel_launch(void* const* d_in, const int* in_sizes, int n_in,
                              void* d_out, int out_size) {
    // C is the largest input; the remaining two are mu, nu in order.
    int ci = 0;
    for (int k = 1; k < n_in; ++k) if (in_sizes[k] > in_sizes[ci]) ci = k;
    const float* in2[2]; int w = 0;
    for (int k = 0; k < n_in && w < 2; ++k) if (k != ci) in2[w++] = (const float*)d_in[k];
    const float* mu = in2[0];
    const float* nu = in2[1];
    const float* C  = (const float*)d_in[ci];

    float* out = (float*)d_out;
    float* cost = nullptr;
    float* pi   = nullptr;
    const int NPI = NB * PP * PP;
    if (out_size >= NPI + NB)      { cost = out;     pi = out + NB; }
    else if (out_size == NPI)      { cost = nullptr; pi = out; }
    else                           { cost = out;     pi = nullptr; }

    init_k<<<(NB * PP + 255) / 256, 256>>>(mu, nu);
    pad_k<<<(CAP * NB * PP + 255) / 256, 256>>>();
    colmin_k<<<dim3(16, 16), 256>>>(C);
    colcnt_k<<<dim3(32, 16), 256>>>(C);
    colscan_k<<<64, 256>>>();
    colwrite_k<<<dim3(32, 16), 256>>>(C);
    rowmincompact_k<<<dim3(128, 16), 256>>>(C);

    iter_k<<<dim3(8, 16), 256>>>();

    finalpass<<<dim3(64, 16), 256>>>(C, pi);
    costred<<<1, 32>>>(cost);
}

// round 16
// speedup vs baseline: 3.5994x; 1.2137x over previous
#include <cuda_runtime.h>
#include <math.h>
#include <cstdint>

#define NB 16
#define PP 1024
#define CAP 96
#define TSEL 0.045f
#define ES (NB * PP)   /* e-plane stride (elements) in sparse tables */

static constexpr float KLOG  = 1442.6950408889634f;   // 1/(EPS*ln2)
static constexpr float NKLOG = -1442.6950408889634f;
static constexpr float LGEPS = 1e-8f;

// Persistent scratch (module globals; no runtime allocation)
__device__ float g_uK[NB * PP];
__device__ float g_vK[NB * PP];
__device__ float g_logmu2[NB * PP];
__device__ float g_lognu2[NB * PP];
__device__ float g_cmin[NB * PP];
__device__ float g_cminK[NB * PP];
__device__ float g_rminK[NB * PP];
__device__ uint2 g_cte[CAP * NB * PP];   // packed {t=(min-C)*K, row idx}, [e][n][j]
__device__ uint2 g_rte[CAP * NB * PP];   // packed {t, col idx},            [e][n][i]
__device__ int   g_ccnt[NB * PP];
__device__ int   g_rcnt[NB * PP];
__device__ int   g_ccnt8[NB * 8 * PP];
__device__ int   g_coff8[NB * 8 * PP];
__device__ float g_part[NB * 64];
__device__ float g_cost[NB];

__device__ __forceinline__ float ex2f(float x) {
    float y; asm("ex2.approx.ftz.f32 %0, %1;" : "=f"(y) : "f"(x)); return y;
}
__device__ __forceinline__ float lg2f(float x) {
    float y; asm("lg2.approx.ftz.f32 %0, %1;" : "=f"(y) : "f"(x)); return y;
}

__device__ __forceinline__ unsigned int smem_u32(const void* p) {
    unsigned int a;
    asm("{ .reg .u64 t; cvta.to.shared.u64 t, %1; cvt.u32.u64 %0, t; }"
        : "=r"(a) : "l"(p));
    return a;
}

// DSMEM scatter: store f32 into cluster-rank `rank`'s copy of local smem addr.
__device__ __forceinline__ void dsmem_st_f32(unsigned int local_addr, unsigned int rank, float v) {
    unsigned int rem;
    asm volatile("mapa.shared::cluster.u32 %0, %1, %2;"
                 : "=r"(rem) : "r"(local_addr), "r"(rank));
    asm volatile("st.shared::cluster.f32 [%0], %1;" :: "r"(rem), "f"(v) : "memory");
}

// Arrive (release.cluster) on cluster-rank `rank`'s copy of the mbarrier.
__device__ __forceinline__ void mbar_arrive_peer(unsigned int local_addr, unsigned int rank) {
    unsigned int rem;
    asm volatile("mapa.shared::cluster.u32 %0, %1, %2;"
                 : "=r"(rem) : "r"(local_addr), "r"(rank));
    asm volatile("mbarrier.arrive.release.cluster.shared::cluster.b64 _, [%0];"
                 :: "r"(rem) : "memory");
}

// Spin on local mbarrier phase parity with ACQUIRE at cluster scope.
__device__ __forceinline__ void mbar_wait(unsigned int addr, unsigned int parity) {
    asm volatile(
        "{\n\t"
        ".reg .pred P;\n\t"
        "WL%=:\n\t"
        "mbarrier.try_wait.parity.acquire.cluster.shared::cta.b64 P, [%0], %1;\n\t"
        "@!P bra WL%=;\n\t"
        "}"
        :: "r"(addr), "r"(parity) : "memory");
}

__global__ void __launch_bounds__(256) init_k(const float* __restrict__ mu,
                                              const float* __restrict__ nu) {
    int t = blockIdx.x * blockDim.x + threadIdx.x;
    if (t < NB * PP) {
        g_logmu2[t] = log2f(mu[t] + LGEPS);
        g_lognu2[t] = log2f(nu[t] + LGEPS);
    }
}

// Prefill sparse tables so padded entries contribute exactly 0 (ex2(-1e9)->0, FTZ).
__global__ void __launch_bounds__(256) pad_k() {
    int t = blockIdx.x * blockDim.x + threadIdx.x;
    if (t < CAP * NB * PP) {
        uint2 p; p.x = __float_as_uint(-1e9f); p.y = 0;
        g_cte[t] = p; g_rte[t] = p;
    }
}

// ------------------------- per-column min -------------------------
__global__ void __launch_bounds__(256) colmin_k(const float* __restrict__ C) {
    const int n = blockIdx.y, cb = blockIdx.x;
    __shared__ float pm[16 * 64];
    const int tid = threadIdx.x;
    const int cg = tid & 15, rg = tid >> 4;
    const float4* Cp = (const float4*)(C + ((size_t)n << 20)
                       + (size_t)(rg * 64) * PP) + cb * 16 + cg;
    float4 mn = make_float4(1e30f, 1e30f, 1e30f, 1e30f);
#pragma unroll 8
    for (int r = 0; r < 64; ++r) {
        float4 c = Cp[r * (PP / 4)];
        mn.x = fminf(mn.x, c.x); mn.y = fminf(mn.y, c.y);
        mn.z = fminf(mn.z, c.z); mn.w = fminf(mn.w, c.w);
    }
    *(float4*)(pm + rg * 64 + cg * 4) = mn;
    __syncthreads();
    if (tid < 64) {
        float m = pm[tid];
#pragma unroll
        for (int k = 1; k < 16; ++k) m = fminf(m, pm[k * 64 + tid]);
        g_cmin[n * PP + cb * 64 + tid]  = m;
        g_cminK[n * PP + cb * 64 + tid] = KLOG * m;
    }
}

// ---------------- column compaction: count / scan / write ----------------
__global__ void __launch_bounds__(256) colcnt_k(const float* __restrict__ C) {
    const int n = blockIdx.y;
    const int w = blockIdx.x * 256 + threadIdx.x;   // 0..8191
    const int q = w >> 10, j = w & 1023;
    const float th = g_cmin[n * PP + j] + TSEL;
    const float* Cp = C + ((size_t)n << 20) + (size_t)(q * 128) * PP + j;
    int cnt = 0;
#pragma unroll 8
    for (int r = 0; r < 128; ++r) cnt += (Cp[(size_t)r * PP] < th) ? 1 : 0;
    g_ccnt8[(n * 8 + q) * PP + j] = cnt;
}

__global__ void __launch_bounds__(256) colscan_k() {
    int t = blockIdx.x * 256 + threadIdx.x;   // 0..16383
    int n = t >> 10, j = t & 1023;
    int off = 0;
#pragma unroll
    for (int q = 0; q < 8; ++q) {
        g_coff8[(n * 8 + q) * PP + j] = off;
        off += g_ccnt8[(n * 8 + q) * PP + j];
    }
    g_ccnt[n * PP + j] = off < CAP ? off : CAP;
}

__global__ void __launch_bounds__(256) colwrite_k(const float* __restrict__ C) {
    const int n = blockIdx.y;
    const int w = blockIdx.x * 256 + threadIdx.x;
    const int q = w >> 10, j = w & 1023;
    const float mn = g_cmin[n * PP + j];
    const float th = mn + TSEL;
    const float* Cp = C + ((size_t)n << 20) + (size_t)(q * 128) * PP + j;
    int e = g_coff8[(n * 8 + q) * PP + j];
    for (int r = 0; r < 128; ++r) {
        float c = Cp[(size_t)r * PP];
        if (c < th) {
            if (e < CAP) {
                uint2 p;
                p.x = __float_as_uint((mn - c) * KLOG);
                p.y = (unsigned)(q * 128 + r);
                g_cte[e * ES + n * PP + j] = p;
            }
            ++e;
        }
    }
}

// ---------------- fused row min + compaction (warp per row) ----------------
__global__ void __launch_bounds__(256) rowmincompact_k(const float* __restrict__ C) {
    const int n = blockIdx.y;
    const int tid = threadIdx.x, w = tid >> 5, l = tid & 31;
    const int i = blockIdx.x * 8 + w;
    const float* Cr = C + ((size_t)n << 20) + (size_t)i * PP;
    const float4* Cr4 = (const float4*)Cr;
    float m = 1e30f;
#pragma unroll
    for (int k = 0; k < 8; ++k) {
        float4 c = Cr4[l + 32 * k];
        m = fminf(m, fminf(fminf(c.x, c.y), fminf(c.z, c.w)));
    }
#pragma unroll
    for (int o = 16; o; o >>= 1) m = fminf(m, __shfl_xor_sync(0xFFFFFFFFu, m, o));
    if (l == 0) g_rminK[n * PP + i] = KLOG * m;

    const float th = m + TSEL;
    int base = 0;
    for (int cb = 0; cb < 32; ++cb) {
        float c = Cr[cb * 32 + l];
        bool p = c < th;
        unsigned msk = __ballot_sync(0xFFFFFFFFu, p);
        int e = base + __popc(msk & ((1u << l) - 1u));
        if (p && e < CAP) {
            uint2 pk;
            pk.x = __float_as_uint((m - c) * KLOG);
            pk.y = (unsigned)(cb * 32 + l);
            g_rte[e * ES + n * PP + i] = pk;
        }
        base += __popc(msk);
    }
    if (l == 0) g_rcnt[n * PP + i] = base < CAP ? base : CAP;
}

// ---------------------------------------------------------------------------
// Persistent iteration: cluster of 8 CTAs per batch, 256 threads per CTA.
// Duals exchanged via DSMEM scatter (st.shared::cluster) into every CTA's
// full sh_u/sh_v copies; per-CTA 128-max broadcast as one float (bmax). The
// all-to-all mbarrier (release/acquire, count=8) orders the DSMEM stores.
// NO global loads/stores and no L1 flush in the loop -> sparse tables stay
// L1-resident all 100 iterations; phase critical path is DSMEM-latency only.
// ---------------------------------------------------------------------------
__global__ void __launch_bounds__(256) __cluster_dims__(8, 1, 1)
iter_k() {
    const int n   = blockIdx.y;
    const int c   = blockIdx.x;
    const int tid = threadIdx.x;
    const int tl  = tid & 127;          // owned output within CTA block
    const int hi  = tid >> 7;           // 0 = even entries, 1 = odd entries
    const int j   = c * 128 + tl;       // owned col (col phase) / row (row phase)
    const int gi  = n * PP + j;
    __shared__ float sh_u[PP];
    __shared__ float sh_v[PP];
    __shared__ float ss[128];
    __shared__ float pmax[4];
    __shared__ float bmax[8];
    __shared__ __align__(8) unsigned long long mbar;
    const int w = tid >> 5, l = tid & 31;
    const unsigned int mba = smem_u32(&mbar);
    const unsigned int a_shv_j = smem_u32(&sh_v[j]);
    const unsigned int a_shu_j = smem_u32(&sh_u[j]);
    const unsigned int a_bmax  = smem_u32(&bmax[c]);

    if (tid == 0)
        asm volatile("mbarrier.init.shared.b64 [%0], %1;" :: "r"(mba), "r"(8u) : "memory");
    // init full u copy locally: u = 1 -> uK = K
    sh_u[tid]       = KLOG;
    sh_u[tid + 256] = KLOG;
    sh_u[tid + 512] = KLOG;
    sh_u[tid + 768] = KLOG;
    __syncthreads();
    // One-time cluster barrier: publish mbarrier init before any peer arrives.
    asm volatile("barrier.cluster.arrive.aligned;" ::: "memory");
    asm volatile("barrier.cluster.wait.aligned;"   ::: "memory");

    const float cminK = g_cminK[gi];
    const float lognu = g_lognu2[gi];
    const float rminK = g_rminK[gi];
    const float logmu = g_logmu2[gi];
    int ccnt = g_ccnt[gi], rcnt = g_rcnt[gi];
#pragma unroll
    for (int o = 16; o; o >>= 1) {
        ccnt = max(ccnt, __shfl_xor_sync(0xFFFFFFFFu, ccnt, o));
        rcnt = max(rcnt, __shfl_xor_sync(0xFFFFFFFFu, rcnt, o));
    }
    const int cK = (ccnt + 1 - hi) >> 1;   // entries this thread handles
    const int rK = (rcnt + 1 - hi) >> 1;
    const uint2* ctp = g_cte + (size_t)hi * ES + gi;   // start e = hi, step 2
    const uint2* rtp = g_rte + (size_t)hi * ES + gi;
    unsigned int par = 0;
    float Bu = KLOG;    // exact max of u (u = 1 everywhere initially)
    float Bv = 0.f;
    float vout = 0.f, uout = 0.f;

    for (int it = 0; it < 100; ++it) {
        // ---------------- col phase: all u -> v_j ----------------
        {
            float s0 = 0.f, s1 = 0.f;
            int e = 0;
#pragma unroll 2
            for (; e + 1 < cK; e += 2) {
                uint2 p0 = ctp[(size_t)(2 * e) * ES];
                uint2 p1 = ctp[(size_t)(2 * e + 2) * ES];
                s0 += ex2f((sh_u[p0.y] - Bu) + __uint_as_float(p0.x));
                s1 += ex2f((sh_u[p1.y] - Bu) + __uint_as_float(p1.x));
            }
            if (e < cK) {
                uint2 p0 = ctp[(size_t)(2 * e) * ES];
                s0 += ex2f((sh_u[p0.y] - Bu) + __uint_as_float(p0.x));
            }
            float s = s0 + s1;
            if (hi) ss[tl] = s;
            __syncthreads();
            float v;
            if (!hi) {
                v = lognu - (Bu - cminK + lg2f(s + ss[tl]));
                vout = v;
                ss[tl] = v;                 // stage for scatter
                float mx = v;
#pragma unroll
                for (int o = 16; o; o >>= 1) mx = fmaxf(mx, __shfl_xor_sync(0xFFFFFFFFu, mx, o));
                if (l == 0) pmax[w] = mx;
            }
            __syncthreads();
            const float cmax = fmaxf(fmaxf(pmax[0], pmax[1]), fmaxf(pmax[2], pmax[3]));
            // scatter v to ranks hi*4 .. hi*4+3 (covers all 8 across the two halves)
            float vv = ss[tl];
#pragma unroll
            for (int r = 0; r < 4; ++r)
                dsmem_st_f32(a_shv_j, (unsigned int)(hi * 4 + r), vv);
            __syncthreads();               // all scatter stores issued
            if (tid < 8) {
                dsmem_st_f32(a_bmax, (unsigned int)tid, cmax);
                mbar_arrive_peer(mba, (unsigned int)tid);
            }
            mbar_wait(mba, par);
            par ^= 1u;
            Bv = fmaxf(fmaxf(fmaxf(bmax[0], bmax[1]), fmaxf(bmax[2], bmax[3])),
                       fmaxf(fmaxf(bmax[4], bmax[5]), fmaxf(bmax[6], bmax[7])));
        }
        // ---------------- row phase: all v -> u_i ----------------
        {
            float s0 = 0.f, s1 = 0.f;
            int e = 0;
#pragma unroll 2
            for (; e + 1 < rK; e += 2) {
                uint2 p0 = rtp[(size_t)(2 * e) * ES];
                uint2 p1 = rtp[(size_t)(2 * e + 2) * ES];
                s0 += ex2f((sh_v[p0.y] - Bv) + __uint_as_float(p0.x));
                s1 += ex2f((sh_v[p1.y] - Bv) + __uint_as_float(p1.x));
            }
            if (e < rK) {
                uint2 p0 = rtp[(size_t)(2 * e) * ES];
                s0 += ex2f((sh_v[p0.y] - Bv) + __uint_as_float(p0.x));
            }
            float s = s0 + s1;
            if (hi) ss[tl] = s;
            __syncthreads();
            float u;
            if (!hi) {
                u = logmu - (Bv - rminK + lg2f(s + ss[tl]));
                uout = u;
                ss[tl] = u;
                float mx = u;
#pragma unroll
                for (int o = 16; o; o >>= 1) mx = fmaxf(mx, __shfl_xor_sync(0xFFFFFFFFu, mx, o));
                if (l == 0) pmax[w] = mx;
            }
            __syncthreads();
            if (it == 99) break;           // final duals published below
            const float cmax = fmaxf(fmaxf(pmax[0], pmax[1]), fmaxf(pmax[2], pmax[3]));
            float uu = ss[tl];
#pragma unroll
            for (int r = 0; r < 4; ++r)
                dsmem_st_f32(a_shu_j, (unsigned int)(hi * 4 + r), uu);
            __syncthreads();
            if (tid < 8) {
                dsmem_st_f32(a_bmax, (unsigned int)tid, cmax);
                mbar_arrive_peer(mba, (unsigned int)tid);
            }
            mbar_wait(mba, par);
            par ^= 1u;
            Bu = fmaxf(fmaxf(fmaxf(bmax[0], bmax[1]), fmaxf(bmax[2], bmax[3])),
                       fmaxf(fmaxf(bmax[4], bmax[5]), fmaxf(bmax[6], bmax[7])));
        }
    }

    // publish owned slices for finalpass
    if (!hi) {
        g_uK[gi] = uout;
        g_vK[gi] = vout;
    }
}

// ------------------------------- final -----------------------------------
__global__ void __launch_bounds__(256) finalpass(const float* __restrict__ C,
                                                 float* __restrict__ pi) {
    const int n = blockIdx.y, ib = blockIdx.x;
    __shared__ float vsK[PP];
    __shared__ float usr[16];
    __shared__ float red[256];
    const int tid = threadIdx.x;

    for (int j = tid; j < PP; j += 256) vsK[j] = g_vK[n * PP + j];
    if (tid < 16) usr[tid] = g_uK[n * PP + ib * 16 + tid];
    __syncthreads();

    const float4* Cb = (const float4*)(C + ((size_t)n << 20) + (size_t)ib * 16 * PP);
    float4* Pb = pi ? (float4*)(pi + ((size_t)n << 20) + (size_t)ib * 16 * PP) : nullptr;
    const float4* vs4 = (const float4*)vsK;

    float acc = 0.f;
#pragma unroll 4
    for (int e = tid; e < 4096; e += 256) {
        int row = e >> 8;
        int c4  = e & 255;
        float uK = usr[row];
        float4 c  = Cb[e];
        float4 vv = vs4[c4];
        float p0 = ex2f(fmaf(c.x, NKLOG, uK + vv.x));
        float p1 = ex2f(fmaf(c.y, NKLOG, uK + vv.y));
        float p2 = ex2f(fmaf(c.z, NKLOG, uK + vv.z));
        float p3 = ex2f(fmaf(c.w, NKLOG, uK + vv.w));
        acc = fmaf(p0, c.x, acc);
        acc = fmaf(p1, c.y, acc);
        acc = fmaf(p2, c.z, acc);
        acc = fmaf(p3, c.w, acc);
        if (Pb) Pb[e] = make_float4(p0, p1, p2, p3);
    }

    red[tid] = acc;
    __syncthreads();
#pragma unroll
    for (int st = 128; st; st >>= 1) {
        if (tid < st) red[tid] += red[tid + st];
        __syncthreads();
    }
    if (tid == 0) g_part[n * 64 + ib] = red[0];
}

__global__ void costred(float* __restrict__ cost) {
    int n = threadIdx.x;
    if (n < NB) {
        float s = 0.f;
#pragma unroll
        for (int k = 0; k < 64; ++k) s += g_part[n * 64 + k];
        if (cost) cost[n] = s;
        else      g_cost[n] = s;
    }
}

extern "C" void kernel_launch(void* const* d_in, const int* in_sizes, int n_in,
                              void* d_out, int out_size) {
    // C is the largest input; the remaining two are mu, nu in order.
    int ci = 0;
    for (int k = 1; k < n_in; ++k) if (in_sizes[k] > in_sizes[ci]) ci = k;
    const float* in2[2]; int w = 0;
    for (int k = 0; k < n_in && w < 2; ++k) if (k != ci) in2[w++] = (const float*)d_in[k];
    const float* mu = in2[0];
    const float* nu = in2[1];
    const float* C  = (const float*)d_in[ci];

    float* out = (float*)d_out;
    float* cost = nullptr;
    float* pi   = nullptr;
    const int NPI = NB * PP * PP;
    if (out_size >= NPI + NB)      { cost = out;     pi = out + NB; }
    else if (out_size == NPI)      { cost = nullptr; pi = out; }
    else                           { cost = out;     pi = nullptr; }

    init_k<<<(NB * PP + 255) / 256, 256>>>(mu, nu);
    pad_k<<<(CAP * NB * PP + 255) / 256, 256>>>();
    colmin_k<<<dim3(16, 16), 256>>>(C);
    colcnt_k<<<dim3(32, 16), 256>>>(C);
    colscan_k<<<64, 256>>>();
    colwrite_k<<<dim3(32, 16), 256>>>(C);
    rowmincompact_k<<<dim3(128, 16), 256>>>(C);

    iter_k<<<dim3(8, 16), 256>>>();

    finalpass<<<dim3(64, 16), 256>>>(C, pi);
    costred<<<1, 32>>>(cost);
}